// round 16
// baseline (speedup 1.0000x reference)
#include <cuda_runtime.h>
#include <cuda_fp16.h>
#include <cstdint>
#include <math.h>

#define BATCH   16384
#define TSTEPS  28
#define FEAT    28
#define HID     128
#define G3      384
#define NCLS    10

#define TILE_B  16
#define NTH     256
#define NKT     10          // K chunks of 16: kt 0..7 = h (k=j), kt 8,9 = x
#define NBLK    (BATCH / TILE_B)
#define NBFR4   (8 * NKT * 4 * 32)   // paired fragments

// B operand (fp16), fragment-linear, nt-PAIRED:
// index [w(8)][kt(10)][g(4)][lane(32)] : uint4 {nt0.b0, nt0.b1, nt1.b0, nt1.b1}
__device__ __align__(16) uint4 gB4[NBFR4];

__device__ __forceinline__ void mma16816(float* c, const uint4& a,
                                         uint32_t b0, uint32_t b1) {
    asm volatile(
        "mma.sync.aligned.m16n8k16.row.col.f32.f16.f16.f32 "
        "{%0,%1,%2,%3}, {%4,%5,%6,%7}, {%8,%9}, {%0,%1,%2,%3};"
        : "+f"(c[0]), "+f"(c[1]), "+f"(c[2]), "+f"(c[3])
        : "r"(a.x), "r"(a.y), "r"(a.z), "r"(a.w), "r"(b0), "r"(b1));
}

// HW tanh, packed fp16x2: 1 MUFU op for TWO elements
__device__ __forceinline__ __half2 tanh2_hw(__half2 v) {
    __half2 r;
    asm("tanh.approx.f16x2 %0, %1;"
        : "=r"(*(uint32_t*)&r) : "r"(*(uint32_t*)&v));
    return r;
}

// ---------------------------------------------------------------------------
// Prep: weights -> nt-paired fragment-linear fp16 (unchanged layout).
// g: 0=z(col j), 1=r(col 128+j), 2=rh(col 256+j, R rows), 3=xh(col 256+j, W rows)
// ---------------------------------------------------------------------------
__global__ void prep_B(const float* __restrict__ Rk, const float* __restrict__ Wk) {
    int idx = blockIdx.x * blockDim.x + threadIdx.x;
    if (idx >= NBFR4) return;
    int lane = idx & 31;
    int g    = (idx >> 5) & 3;
    int kt   = (idx >> 7) % NKT;
    int w    = (idx >> 7) / NKT;
    int gid  = lane >> 2, tg = lane & 3;
    int k0   = kt * 16 + tg * 2;

    uint32_t words[2][2];
#pragma unroll
    for (int nt = 0; nt < 2; nt++) {
        int jloc = 16 * w + 8 * nt + gid;
        int wcol = (g == 0) ? jloc : (g == 1 ? 128 + jloc : 256 + jloc);
        __half h[4];
#pragma unroll
        for (int i = 0; i < 4; i++) {
            int k = k0 + (i >> 1) * 8 + (i & 1);
            float val = 0.0f;
            if (k < HID) { if (g != 3) val = Rk[k * G3 + wcol]; }
            else { int f = k - HID; if (f < FEAT && g != 2) val = Wk[f * G3 + wcol]; }
            h[i] = __float2half_rn(val);
        }
        words[nt][0] = (uint32_t)(*(unsigned short*)&h[0]) |
                       ((uint32_t)(*(unsigned short*)&h[1]) << 16);
        words[nt][1] = (uint32_t)(*(unsigned short*)&h[2]) |
                       ((uint32_t)(*(unsigned short*)&h[3]) << 16);
    }
    gB4[idx] = make_uint4(words[0][0], words[0][1], words[1][0], words[1][1]);
}

// ---------------------------------------------------------------------------
// Main fused GRU: persistent per-block scan, HMMA core.
// Round 16: TILE_B=16 (mt dropped) -> 32 acc regs, occ-3 target,
//           1024 fine-grained blocks for 98.8% wave balance.
// ---------------------------------------------------------------------------
__global__ void __launch_bounds__(NTH, 3)
gru_hmma_kernel(const float* __restrict__ x,
                const float* __restrict__ bias,
                const float* __restrict__ dw,
                const float* __restrict__ db,
                float* __restrict__ out)
{
    __shared__ uint4 Ah[2][NKT][32];         // [buf][kt][lane], fp16 frags
    __shared__ float hs[TILE_B][HID + 1];

    const int tid  = threadIdx.x;
    const int wid  = tid >> 5;
    const int lane = tid & 31;
    const int gid  = lane >> 2;
    const int tg   = lane & 3;
    const int b0   = blockIdx.x * TILE_B;
    const float* xg = x + (size_t)b0 * (TSTEPS * FEAT);

    // zero buffer 0 (h region must start as 0; buf 1 fully written in step 0)
    for (int i = tid; i < NKT * 32; i += NTH)
        ((uint4*)Ah[0])[i] = make_uint4(0, 0, 0, 0);

    // biases packed fp16x2 per u = g*2+nt (added in the fp16 epilogue)
    uint32_t bp2[8];
#pragma unroll
    for (int g = 0; g < 4; g++)
#pragma unroll
        for (int nt = 0; nt < 2; nt++) {
            int jl = 16 * wid + 8 * nt + 2 * tg;
            float v[2];
#pragma unroll
            for (int e = 0; e < 2; e++) {
                int j = jl + e;
                if      (g == 0) v[e] = bias[j]       + bias[G3 + j];
                else if (g == 1) v[e] = bias[128 + j] + bias[G3 + 128 + j];
                else if (g == 2) v[e] = bias[G3 + 256 + j];
                else             v[e] = bias[256 + j];
            }
            __half2 h2 = __floats2half2_rn(v[0], v[1]);
            bp2[g * 2 + nt] = *(uint32_t*)&h2;
        }

    // per-thread x staging geometry (1 slot/thread; 2*32*4 = 256 slots)
    const int xr   = tid & 3;
    const int xln  = (tid >> 2) & 31;
    const int xkt8 = tid >> 7;            // 0..1
    const int xgd  = xln >> 2, xtgg = xln & 3;
    const int xrow = xgd + 8 * (xr & 1);
    const int xkl  = xkt8 * 16 + xtgg * 2 + 8 * (xr >> 1);

    auto ld_x = [&](int t, float& v0, float& v1) {
        v0 = 0.0f; v1 = 0.0f;
        if (xkl < FEAT) {
            const float* p = xg + (size_t)xrow * (TSTEPS * FEAT) + t * FEAT + xkl;
            v0 = __ldg(p);
            if (xkl + 1 < FEAT) v1 = __ldg(p + 1);
        }
    };
    auto st_x = [&](int buf, float v0, float v1) {
        __half2 hx = __floats2half2_rn(v0, v1);  // low = k, high = k+1
        ((uint32_t*)&Ah[buf][8 + xkt8][xln])[xr] = *(uint32_t*)&hx;
    };

    {   // stage x(0) into buffer 0
        float v0, v1;
        ld_x(0, v0, v1);
        st_x(0, v0, v1);
    }
    __syncthreads();

    float acc[8][4];
    const __half2 H05 = __float2half2_rn(0.5f);

#pragma unroll 1
    for (int t = 0; t < TSTEPS; t++) {
        const int p = t & 1;         // read buffer
        const int q = p ^ 1;         // write buffer (next step's read)

        // prefetch x(t+1) into registers (latency hidden behind mainloop MMAs)
        float pv0 = 0.0f, pv1 = 0.0f;
        if (t < TSTEPS - 1) ld_x(t + 1, pv0, pv1);

        // preload this warp's old-h fragment (kt = wid) for the epilogue
        const uint4 oldh = Ah[p][wid][lane];

#pragma unroll
        for (int u = 0; u < 8; u++)
#pragma unroll
            for (int i = 0; i < 4; i++) acc[u][i] = 0.0f;

        // ---- HMMA mainloop (reads buf p): 6 MMAs per kt ----
#pragma unroll
        for (int kt = 0; kt < NKT; kt++) {
            const uint4 A = Ah[p][kt][lane];
            // active gate groups: kt<8 -> {z, r, rh}; kt>=8 -> {z, r, xh}
            const int g2 = (kt < 8) ? 2 : 3;
            const int gs[3] = {0, 1, g2};

            uint4 B[3];
#pragma unroll
            for (int gi = 0; gi < 3; gi++)
                B[gi] = __ldg(&gB4[((wid * NKT + kt) * 4 + gs[gi]) * 32 + lane]);

#pragma unroll
            for (int gi = 0; gi < 3; gi++) {
                const int u0 = gs[gi] * 2, u1 = u0 + 1;
                mma16816(acc[u0], A, B[gi].x, B[gi].y);
                mma16816(acc[u1], A, B[gi].z, B[gi].w);
            }
        }
        // NO barrier here: epilogue writes go to buf q, mainloop readers use buf p.

        // ---- epilogue (fp16x2): gates packed 2-wide; output pre-packed ----
        {
            const uint32_t hh_[4] = {oldh.x, oldh.y, oldh.z, oldh.w};
            uint32_t nh[4];
#pragma unroll
            for (int r = 0; r < 4; r++) {
                const int nt = r >> 1;
                const int ci = (r & 1) * 2;
                __half2 az2 = __hadd2(__floats2half2_rn(acc[0 + nt][ci], acc[0 + nt][ci + 1]),
                                      *(__half2*)&bp2[0 + nt]);
                __half2 ar2 = __hadd2(__floats2half2_rn(acc[2 + nt][ci], acc[2 + nt][ci + 1]),
                                      *(__half2*)&bp2[2 + nt]);
                __half2 ah2 = __hadd2(__floats2half2_rn(acc[4 + nt][ci], acc[4 + nt][ci + 1]),
                                      *(__half2*)&bp2[4 + nt]);
                __half2 ax2 = __hadd2(__floats2half2_rn(acc[6 + nt][ci], acc[6 + nt][ci + 1]),
                                      *(__half2*)&bp2[6 + nt]);
                __half2 z2 = __hfma2(tanh2_hw(__hmul2(az2, H05)), H05, H05);
                __half2 r2 = __hfma2(tanh2_hw(__hmul2(ar2, H05)), H05, H05);
                __half2 hc2 = tanh2_hw(__hfma2(r2, ah2, ax2));
                __half2 hold2 = *(__half2*)&hh_[r];
                __half2 hn2 = __hfma2(z2, __hsub2(hold2, hc2), hc2);
                nh[r] = *(uint32_t*)&hn2;
                if (t == TSTEPS - 1) {
                    float2 f = __half22float2(hn2);
                    int row = gid + 8 * (r & 1);
                    int j   = 16 * wid + 8 * nt + 2 * tg;
                    hs[row][j]     = f.x;
                    hs[row][j + 1] = f.y;
                }
            }
            Ah[q][wid][lane] = make_uint4(nh[0], nh[1], nh[2], nh[3]);
        }

        if (t < TSTEPS - 1) st_x(q, pv0, pv1);
        __syncthreads();   // buf q complete + all buf p reads done -> next step
    }

    // ---- dense + softmax ----
    if (tid < TILE_B) {
        const int row = tid;
        float lg[NCLS];
#pragma unroll
        for (int c = 0; c < NCLS; c++) lg[c] = db[c];
        for (int j = 0; j < HID; j++) {
            float hv = hs[row][j];
#pragma unroll
            for (int c = 0; c < NCLS; c++) lg[c] = fmaf(hv, dw[j * NCLS + c], lg[c]);
        }
        float m = lg[0];
#pragma unroll
        for (int c = 1; c < NCLS; c++) m = fmaxf(m, lg[c]);
        float s = 0.0f;
#pragma unroll
        for (int c = 0; c < NCLS; c++) { lg[c] = expf(lg[c] - m); s += lg[c]; }
        float inv = __fdividef(1.0f, s);
#pragma unroll
        for (int c = 0; c < NCLS; c++)
            out[(size_t)(b0 + row) * NCLS + c] = lg[c] * inv;
    }
}

extern "C" void kernel_launch(void* const* d_in, const int* in_sizes, int n_in,
                              void* d_out, int out_size) {
    const float* x    = (const float*)d_in[0];
    const float* Wk   = (const float*)d_in[1];
    const float* Rk   = (const float*)d_in[2];
    const float* bias = (const float*)d_in[3];
    const float* dw   = (const float*)d_in[4];
    const float* db   = (const float*)d_in[5];
    float* out = (float*)d_out;

    prep_B<<<(NBFR4 + 255) / 256, 256>>>(Rk, Wk);
    gru_hmma_kernel<<<NBLK, NTH>>>(x, bias, dw, db, out);
}

// round 17
// speedup vs baseline: 1.3211x; 1.3211x over previous
#include <cuda_runtime.h>
#include <cuda_fp16.h>
#include <cstdint>
#include <math.h>

#define BATCH   16384
#define TSTEPS  28
#define FEAT    28
#define HID     128
#define G3      384
#define NCLS    10

#define TILE_B  32
#define NTH     256
#define NKT     10          // K chunks of 16: kt 0..7 = h (k=j), kt 8,9 = x
#define NBLK    (BATCH / TILE_B)
#define NBFR4   (8 * NKT * 4 * 32)   // paired fragments

// B operand (fp16), fragment-linear, nt-PAIRED:
// index [w(8)][kt(10)][g(4)][lane(32)] : uint4 {nt0.b0, nt0.b1, nt1.b0, nt1.b1}
__device__ __align__(16) uint4 gB4[NBFR4];

// f32-accumulator HMMA (tanh path: rh/xh)
__device__ __forceinline__ void mma16816(float* c, const uint4& a,
                                         uint32_t b0, uint32_t b1) {
    asm volatile(
        "mma.sync.aligned.m16n8k16.row.col.f32.f16.f16.f32 "
        "{%0,%1,%2,%3}, {%4,%5,%6,%7}, {%8,%9}, {%0,%1,%2,%3};"
        : "+f"(c[0]), "+f"(c[1]), "+f"(c[2]), "+f"(c[3])
        : "r"(a.x), "r"(a.y), "r"(a.z), "r"(a.w), "r"(b0), "r"(b1));
}
// f16-accumulator HMMA (sigmoid gates: z/r). reg0 = rows gid, cols {2tg,2tg+1}
// packed f16x2; reg1 = rows gid+8. Matches the epilogue half2 pairing exactly.
__device__ __forceinline__ void mma16816h(uint32_t* c, const uint4& a,
                                          uint32_t b0, uint32_t b1) {
    asm volatile(
        "mma.sync.aligned.m16n8k16.row.col.f16.f16.f16.f16 "
        "{%0,%1}, {%2,%3,%4,%5}, {%6,%7}, {%0,%1};"
        : "+r"(c[0]), "+r"(c[1])
        : "r"(a.x), "r"(a.y), "r"(a.z), "r"(a.w), "r"(b0), "r"(b1));
}

// HW tanh, packed fp16x2: 1 MUFU op for TWO elements
__device__ __forceinline__ __half2 tanh2_hw(__half2 v) {
    __half2 r;
    asm("tanh.approx.f16x2 %0, %1;"
        : "=r"(*(uint32_t*)&r) : "r"(*(uint32_t*)&v));
    return r;
}

// ---------------------------------------------------------------------------
// Prep: weights -> nt-paired fragment-linear fp16 (unchanged layout).
// g: 0=z(col j), 1=r(col 128+j), 2=rh(col 256+j, R rows), 3=xh(col 256+j, W rows)
// ---------------------------------------------------------------------------
__global__ void prep_B(const float* __restrict__ Rk, const float* __restrict__ Wk) {
    int idx = blockIdx.x * blockDim.x + threadIdx.x;
    if (idx >= NBFR4) return;
    int lane = idx & 31;
    int g    = (idx >> 5) & 3;
    int kt   = (idx >> 7) % NKT;
    int w    = (idx >> 7) / NKT;
    int gid  = lane >> 2, tg = lane & 3;
    int k0   = kt * 16 + tg * 2;

    uint32_t words[2][2];
#pragma unroll
    for (int nt = 0; nt < 2; nt++) {
        int jloc = 16 * w + 8 * nt + gid;
        int wcol = (g == 0) ? jloc : (g == 1 ? 128 + jloc : 256 + jloc);
        __half h[4];
#pragma unroll
        for (int i = 0; i < 4; i++) {
            int k = k0 + (i >> 1) * 8 + (i & 1);
            float val = 0.0f;
            if (k < HID) { if (g != 3) val = Rk[k * G3 + wcol]; }
            else { int f = k - HID; if (f < FEAT && g != 2) val = Wk[f * G3 + wcol]; }
            h[i] = __float2half_rn(val);
        }
        words[nt][0] = (uint32_t)(*(unsigned short*)&h[0]) |
                       ((uint32_t)(*(unsigned short*)&h[1]) << 16);
        words[nt][1] = (uint32_t)(*(unsigned short*)&h[2]) |
                       ((uint32_t)(*(unsigned short*)&h[3]) << 16);
    }
    gB4[idx] = make_uint4(words[0][0], words[0][1], words[1][0], words[1][1]);
}

// ---------------------------------------------------------------------------
// Main fused GRU: persistent per-block scan, HMMA core.
// Round 17: R15 base (TILE_B=32, occ 2) + f16-accumulator HMMA for z/r gates
//           (biases folded into acc init; cvt-free sigmoid path).
// ---------------------------------------------------------------------------
__global__ void __launch_bounds__(NTH, 2)
gru_hmma_kernel(const float* __restrict__ x,
                const float* __restrict__ bias,
                const float* __restrict__ dw,
                const float* __restrict__ db,
                float* __restrict__ out)
{
    __shared__ uint4 Ah[2][NKT][2][32];      // [buf][kt][mt][lane], fp16 frags
    __shared__ float hs[TILE_B][HID + 1];

    const int tid  = threadIdx.x;
    const int wid  = tid >> 5;
    const int lane = tid & 31;
    const int gid  = lane >> 2;
    const int tg   = lane & 3;
    const int b0   = blockIdx.x * TILE_B;
    const float* xg = x + (size_t)b0 * (TSTEPS * FEAT);

    // zero buffer 0 (h region must start as 0; buf 1 fully written in step 0)
    for (int i = tid; i < NKT * 2 * 32; i += NTH)
        ((uint4*)Ah[0])[i] = make_uint4(0, 0, 0, 0);

    // z/r biases packed fp16x2 per u = gate*2+nt (acc-init for f16 HMMA)
    uint32_t bp2[4];
#pragma unroll
    for (int g = 0; g < 2; g++)
#pragma unroll
        for (int nt = 0; nt < 2; nt++) {
            int jl = 16 * wid + 8 * nt + 2 * tg;
            float v[2];
#pragma unroll
            for (int e = 0; e < 2; e++) {
                int j = jl + e;
                v[e] = (g == 0) ? (bias[j] + bias[G3 + j])
                                : (bias[128 + j] + bias[G3 + 128 + j]);
            }
            __half2 h2 = __floats2half2_rn(v[0], v[1]);
            bp2[g * 2 + nt] = *(uint32_t*)&h2;
        }
    // rh/xh biases fp32 (acc-init for f32 HMMA): a = 0,1 rh nt0/1; 2,3 xh nt0/1
    float bpf[4][2];
#pragma unroll
    for (int a = 0; a < 4; a++) {
        int nt = a & 1;
        int jl = 16 * wid + 8 * nt + 2 * tg;
#pragma unroll
        for (int e = 0; e < 2; e++) {
            int j = jl + e;
            bpf[a][e] = (a < 2) ? bias[G3 + 256 + j] : bias[256 + j];
        }
    }

    // per-thread x staging geometry (2 slots/thread)
    int xrow[2], xkl[2], xmt[2], xkt8[2], xr[2], xln[2];
#pragma unroll
    for (int i = 0; i < 2; i++) {
        int s   = tid * 2 + i;
        xr[i]   = s & 3;
        xln[i]  = (s >> 2) & 31;
        xmt[i]  = (s >> 7) & 1;
        xkt8[i] = s >> 8;
        int gd = xln[i] >> 2, tgg = xln[i] & 3;
        xrow[i] = xmt[i] * 16 + gd + 8 * (xr[i] & 1);
        xkl[i]  = xkt8[i] * 16 + tgg * 2 + 8 * (xr[i] >> 1);
    }

    auto ld_x = [&](int t, float* v0, float* v1) {
#pragma unroll
        for (int i = 0; i < 2; i++) {
            v0[i] = 0.0f; v1[i] = 0.0f;
            if (xkl[i] < FEAT) {
                const float* p = xg + (size_t)xrow[i] * (TSTEPS * FEAT) + t * FEAT + xkl[i];
                v0[i] = __ldg(p);
                if (xkl[i] + 1 < FEAT) v1[i] = __ldg(p + 1);
            }
        }
    };
    auto st_x = [&](int buf, const float* v0, const float* v1) {
#pragma unroll
        for (int i = 0; i < 2; i++) {
            __half2 hx = __floats2half2_rn(v0[i], v1[i]);
            ((uint32_t*)&Ah[buf][8 + xkt8[i]][xmt[i]][xln[i]])[xr[i]] = *(uint32_t*)&hx;
        }
    };

    {   // stage x(0) into buffer 0
        float v0[2], v1[2];
        ld_x(0, v0, v1);
        st_x(0, v0, v1);
    }
    __syncthreads();

    // accumulators: f16 for z/r ([mt][u:z0,z1,r0,r1][2 regs]); f32 for rh/xh
    uint32_t accH[2][4][2];
    float    accF[2][4][4];   // [mt][a: rh nt0, rh nt1, xh nt0, xh nt1][4]
    const __half2 H05 = __float2half2_rn(0.5f);

#pragma unroll 1
    for (int t = 0; t < TSTEPS; t++) {
        const int p = t & 1;         // read buffer
        const int q = p ^ 1;         // write buffer (next step's read)

        // prefetch x(t+1) into registers (latency hidden behind mainloop MMAs)
        float pv0[2], pv1[2];
        if (t < TSTEPS - 1) ld_x(t + 1, pv0, pv1);

        // preload this warp's old-h fragments (kt = wid) for the epilogue
        const uint4 oldh0 = Ah[p][wid][0][lane];
        const uint4 oldh1 = Ah[p][wid][1][lane];

#pragma unroll
        for (int mt = 0; mt < 2; mt++) {
#pragma unroll
            for (int u = 0; u < 4; u++) {
                accH[mt][u][0] = bp2[u];     // rows gid half
                accH[mt][u][1] = bp2[u];     // rows gid+8 half
            }
#pragma unroll
            for (int a = 0; a < 4; a++) {
                accF[mt][a][0] = bpf[a][0]; accF[mt][a][1] = bpf[a][1];
                accF[mt][a][2] = bpf[a][0]; accF[mt][a][3] = bpf[a][1];
            }
        }

        // ---- HMMA mainloop (reads buf p) ----
#pragma unroll
        for (int kt = 0; kt < NKT; kt++) {
            const uint4 A0 = Ah[p][kt][0][lane];
            const uint4 A1 = Ah[p][kt][1][lane];
            // active gate groups: kt<8 -> {z, r, rh}; kt>=8 -> {z, r, xh}
            const int g2 = (kt < 8) ? 2 : 3;

            uint4 B[3];
            B[0] = __ldg(&gB4[((wid * NKT + kt) * 4 + 0) * 32 + lane]);
            B[1] = __ldg(&gB4[((wid * NKT + kt) * 4 + 1) * 32 + lane]);
            B[2] = __ldg(&gB4[((wid * NKT + kt) * 4 + g2) * 32 + lane]);

            // z, r: f16-accumulator HMMA
#pragma unroll
            for (int gi = 0; gi < 2; gi++) {
                mma16816h(accH[0][gi * 2 + 0], A0, B[gi].x, B[gi].y);
                mma16816h(accH[1][gi * 2 + 0], A1, B[gi].x, B[gi].y);
                mma16816h(accH[0][gi * 2 + 1], A0, B[gi].z, B[gi].w);
                mma16816h(accH[1][gi * 2 + 1], A1, B[gi].z, B[gi].w);
            }
            // rh / xh: f32-accumulator HMMA
            const int a0 = (g2 - 2) * 2;
            mma16816(accF[0][a0 + 0], A0, B[2].x, B[2].y);
            mma16816(accF[1][a0 + 0], A1, B[2].x, B[2].y);
            mma16816(accF[0][a0 + 1], A0, B[2].z, B[2].w);
            mma16816(accF[1][a0 + 1], A1, B[2].z, B[2].w);
        }
        // NO barrier here: epilogue writes go to buf q, mainloop readers use buf p.

        // ---- epilogue (fp16x2): z/r already packed from f16 HMMA ----
#pragma unroll
        for (int mt = 0; mt < 2; mt++) {
            const uint4 Hh = (mt == 0) ? oldh0 : oldh1;
            const uint32_t hh_[4] = {Hh.x, Hh.y, Hh.z, Hh.w};
            uint32_t nh[4];
#pragma unroll
            for (int r = 0; r < 4; r++) {
                const int nt = r >> 1;
                const int rs = r & 1;          // f16 C reg: 0 = rows gid, 1 = rows gid+8
                const int ci = rs * 2;         // f32 C index base
                __half2 az2 = *(__half2*)&accH[mt][0 + nt][rs];
                __half2 ar2 = *(__half2*)&accH[mt][2 + nt][rs];
                __half2 ah2 = __floats2half2_rn(accF[mt][0 + nt][ci], accF[mt][0 + nt][ci + 1]);
                __half2 ax2 = __floats2half2_rn(accF[mt][2 + nt][ci], accF[mt][2 + nt][ci + 1]);
                __half2 z2 = __hfma2(tanh2_hw(__hmul2(az2, H05)), H05, H05);
                __half2 r2 = __hfma2(tanh2_hw(__hmul2(ar2, H05)), H05, H05);
                __half2 hc2 = tanh2_hw(__hfma2(r2, ah2, ax2));
                __half2 hold2 = *(__half2*)&hh_[r];
                __half2 hn2 = __hfma2(z2, __hsub2(hold2, hc2), hc2);
                nh[r] = *(uint32_t*)&hn2;
                if (t == TSTEPS - 1) {
                    float2 f = __half22float2(hn2);
                    int row = mt * 16 + gid + 8 * (r & 1);
                    int j   = 16 * wid + 8 * nt + 2 * tg;
                    hs[row][j]     = f.x;
                    hs[row][j + 1] = f.y;
                }
            }
            Ah[q][wid][mt][lane] = make_uint4(nh[0], nh[1], nh[2], nh[3]);
        }

        if (t < TSTEPS - 1) st_x(q, pv0, pv1);
        __syncthreads();   // buf q complete + all buf p reads done -> next step
    }

    // ---- dense + softmax ----
    if (tid < TILE_B) {
        const int row = tid;
        float lg[NCLS];
#pragma unroll
        for (int c = 0; c < NCLS; c++) lg[c] = db[c];
        for (int j = 0; j < HID; j++) {
            float hv = hs[row][j];
#pragma unroll
            for (int c = 0; c < NCLS; c++) lg[c] = fmaf(hv, dw[j * NCLS + c], lg[c]);
        }
        float m = lg[0];
#pragma unroll
        for (int c = 1; c < NCLS; c++) m = fmaxf(m, lg[c]);
        float s = 0.0f;
#pragma unroll
        for (int c = 0; c < NCLS; c++) { lg[c] = expf(lg[c] - m); s += lg[c]; }
        float inv = __fdividef(1.0f, s);
#pragma unroll
        for (int c = 0; c < NCLS; c++)
            out[(size_t)(b0 + row) * NCLS + c] = lg[c] * inv;
    }
}

extern "C" void kernel_launch(void* const* d_in, const int* in_sizes, int n_in,
                              void* d_out, int out_size) {
    const float* x    = (const float*)d_in[0];
    const float* Wk   = (const float*)d_in[1];
    const float* Rk   = (const float*)d_in[2];
    const float* bias = (const float*)d_in[3];
    const float* dw   = (const float*)d_in[4];
    const float* db   = (const float*)d_in[5];
    float* out = (float*)d_out;

    prep_B<<<(NBFR4 + 255) / 256, 256>>>(Rk, Wk);
    gru_hmma_kernel<<<NBLK, NTH>>>(x, bias, dw, db, out);
}